// round 16
// baseline (speedup 1.0000x reference)
#include <cuda_runtime.h>
#include <math.h>

#define Bsz 2
#define Lsz 2048
#define Dsz 1024
#define Hn  16
#define HDs 64
#define KTOPn 409
#define BHn (Bsz*Hn)
#define SCALE 0.125f
#define HBINS 2048
#define HBINW 0.08f
#define RMARGIN 0.2f

// ---------------- scratch (device globals: allocation-free rule) ----------------
__device__ float g_Q[Bsz*Lsz*Dsz];
__device__ float g_K[Bsz*Lsz*Dsz];
__device__ float g_V[Bsz*Lsz*Dsz];
__device__ float g_A[Bsz*Lsz*Dsz];       // attention output, [B,L,H*HD]
__device__ float g_norm[BHn*Lsz];
__device__ int   g_sel[BHn*KTOPn];
__device__ float g_part[Bsz*32*Dsz];
__device__ float g_vmean[Bsz*Dsz];
__device__ float g_thr[BHn];
__device__ int   g_list[BHn*Lsz];
__device__ int   g_count[1];

// Side streams + events for fork-join overlap (static init: no device memory,
// identical launched work every call -> deterministic & graph-capturable).
struct OverlapRes {
    cudaStream_t side1, side2;
    cudaEvent_t evV, evQ, evFill, evSel;
    OverlapRes() {
        cudaStreamCreateWithFlags(&side1, cudaStreamNonBlocking);
        cudaStreamCreateWithFlags(&side2, cudaStreamNonBlocking);
        cudaEventCreateWithFlags(&evV, cudaEventDisableTiming);
        cudaEventCreateWithFlags(&evQ, cudaEventDisableTiming);
        cudaEventCreateWithFlags(&evFill, cudaEventDisableTiming);
        cudaEventCreateWithFlags(&evSel, cudaEventDisableTiming);
    }
};
static OverlapRes g_ov;

#define CVT_TF32(dst, src) asm("cvt.rna.tf32.f32 %0, %1;" : "=r"(dst) : "f"(src))

#define MMA_TF32(cc, aa, bb)                                                  \
    asm volatile(                                                             \
        "mma.sync.aligned.m16n8k8.row.col.f32.tf32.tf32.f32 "                 \
        "{%0,%1,%2,%3}, {%4,%5,%6,%7}, {%8,%9}, {%0,%1,%2,%3};"               \
        : "+f"(cc[0]), "+f"(cc[1]), "+f"(cc[2]), "+f"(cc[3])                  \
        : "r"(aa[0]), "r"(aa[1]), "r"(aa[2]), "r"(aa[3]),                     \
          "r"(bb[0]), "r"(bb[1]))

// ------------- 1xTF32 tensor-core GEMM (R12-proven, frozen) --------------------
__global__ __launch_bounds__(256)
void gemm_1xtf32(const float* __restrict__ A, const float* __restrict__ W,
                 const float* __restrict__ bias, float* __restrict__ C,
                 int M, int N, int K) {
    __shared__ float As[128][36];
    __shared__ float Bs[128][36];
    int tid = threadIdx.x;
    int bm = blockIdx.y * 128, bn = blockIdx.x * 128;
    int wid = tid >> 5, lane = tid & 31;
    int wm = (wid & 3) * 32, wn = (wid >> 2) * 64;
    int group = lane >> 2, tg = lane & 3;

    float c[2][8][4];
#pragma unroll
    for (int mt = 0; mt < 2; mt++)
#pragma unroll
        for (int nt = 0; nt < 8; nt++)
#pragma unroll
            for (int i = 0; i < 4; i++) c[mt][nt][i] = 0.f;

    for (int kk = 0; kk < K; kk += 32) {
#pragma unroll
        for (int i = 0; i < 4; i++) {
            int lin = tid + i * 256;
            int r = lin >> 3, c4 = (lin & 7) * 4;
            float4 av = *(const float4*)&A[(size_t)(bm + r) * K + kk + c4];
            float4 wv = *(const float4*)&W[(size_t)(bn + r) * K + kk + c4];
            uint4 at, bt;
            CVT_TF32(at.x, av.x); CVT_TF32(at.y, av.y);
            CVT_TF32(at.z, av.z); CVT_TF32(at.w, av.w);
            CVT_TF32(bt.x, wv.x); CVT_TF32(bt.y, wv.y);
            CVT_TF32(bt.z, wv.z); CVT_TF32(bt.w, wv.w);
            *(uint4*)&As[r][c4] = at;
            *(uint4*)&Bs[r][c4] = bt;
        }
        __syncthreads();

#pragma unroll
        for (int ks = 0; ks < 4; ks++) {
            int k = ks * 8;
            unsigned a[2][4], b[8][2];
#pragma unroll
            for (int mt = 0; mt < 2; mt++) {
                int row = wm + mt * 16 + group;
                a[mt][0] = __float_as_uint(As[row][k + tg]);
                a[mt][1] = __float_as_uint(As[row + 8][k + tg]);
                a[mt][2] = __float_as_uint(As[row][k + tg + 4]);
                a[mt][3] = __float_as_uint(As[row + 8][k + tg + 4]);
            }
#pragma unroll
            for (int nt = 0; nt < 8; nt++) {
                int col = wn + nt * 8 + group;
                b[nt][0] = __float_as_uint(Bs[col][k + tg]);
                b[nt][1] = __float_as_uint(Bs[col][k + tg + 4]);
            }
#pragma unroll
            for (int mt = 0; mt < 2; mt++)
#pragma unroll
                for (int nt = 0; nt < 8; nt++)
                    MMA_TF32(c[mt][nt], a[mt], b[nt]);
        }
        __syncthreads();
    }

#pragma unroll
    for (int mt = 0; mt < 2; mt++) {
        int row0 = bm + wm + mt * 16 + group;
#pragma unroll
        for (int nt = 0; nt < 8; nt++) {
            int col = bn + wn + nt * 8 + tg * 2;
            float b0 = bias[col], b1 = bias[col + 1];
            *(float2*)&C[(size_t)row0 * N + col] =
                make_float2(c[mt][nt][0] + b0, c[mt][nt][1] + b1);
            *(float2*)&C[(size_t)(row0 + 8) * N + col] =
                make_float2(c[mt][nt][2] + b0, c[mt][nt][3] + b1);
        }
    }
}

// ---------------- per-(b,h,l) squared L2 norm of q; also zeroes refine counter -
__global__ void qnorm_kernel(const float* __restrict__ Q, float* __restrict__ norms,
                             int* __restrict__ cnt) {
    if (blockIdx.x == 0 && threadIdx.x == 0) cnt[0] = 0;
    int gw = blockIdx.x * 8 + (threadIdx.x >> 5);
    int lane = threadIdx.x & 31;
    if (gw >= BHn * Lsz) return;
    int l = gw % Lsz;
    int h = (gw / Lsz) % Hn;
    int b = gw / (Lsz * Hn);
    const float* row = Q + (size_t)(b * Lsz + l) * Dsz + h * HDs;
    float v0 = row[lane], v1 = row[lane + 32];
    float ss = v0*v0 + v1*v1;
#pragma unroll
    for (int o = 16; o; o >>= 1) ss += __shfl_xor_sync(0xffffffffu, ss, o);
    if (lane == 0) norms[(b * Hn + h) * Lsz + l] = ss;
}

// ---------------- histogram threshold per (b,h): t within 0.04 of 409th -------
__global__ void hist_thresh_kernel(const float* __restrict__ norms,
                                   float* __restrict__ thr) {
    __shared__ int hist[HBINS];
    __shared__ int chunk[256];
    int bh = blockIdx.x, tid = threadIdx.x;
    const float* nb = norms + (size_t)bh * Lsz;
#pragma unroll
    for (int i = 0; i < HBINS / 256; i++) hist[tid + i * 256] = 0;
    __syncthreads();
    for (int i = tid; i < Lsz; i += 256) {
        int bin = (int)(nb[i] * (1.0f / HBINW));
        bin = min(HBINS - 1, max(0, bin));
        atomicAdd(&hist[bin], 1);
    }
    __syncthreads();
    int cs = 0;
#pragma unroll
    for (int j = 0; j < 8; j++) cs += hist[tid * 8 + j];
    chunk[tid] = cs;
    __syncthreads();
    if (tid == 0) {
        int cum = 0, binfound = 0;
        for (int cidx = 255; cidx >= 0; cidx--) {
            if (cum + chunk[cidx] >= KTOPn) {
                for (int bin = cidx * 8 + 7; bin >= cidx * 8; bin--) {
                    cum += hist[bin];
                    if (cum >= KTOPn) { binfound = bin; break; }
                }
                break;
            }
            cum += chunk[cidx];
        }
        thr[bh] = (binfound + 0.5f) * HBINW;
    }
}

// ---------------- flag boundary-uncertain rows into compact worklist -----------
__global__ void flag_kernel(const float* __restrict__ norms, const float* __restrict__ thr,
                            int* __restrict__ list, int* __restrict__ cnt) {
    int idx = blockIdx.x * 256 + threadIdx.x;
    if (idx >= BHn * Lsz) return;
    float n = norms[idx];
    float t = thr[idx >> 11];
    if (fabsf(n - t) < RMARGIN) {
        int p = atomicAdd(cnt, 1);
        list[p] = idx;
    }
}

// ---------------- exact fp32 norm recompute for flagged rows (coalesced) -------
__global__ __launch_bounds__(256)
void refine_kernel(const float* __restrict__ x, const float* __restrict__ Wq,
                   const float* __restrict__ bq, const int* __restrict__ list,
                   const int* __restrict__ cnt, float* __restrict__ norms) {
    __shared__ float xs[Dsz];
    __shared__ float acc[8];
    int tid = threadIdx.x, wid = tid >> 5, lane = tid & 31;
    int n_items = cnt[0];
    for (int ii = blockIdx.x; ii < n_items; ii += gridDim.x) {
        int idx = list[ii];
        int bh = idx >> 11, l = idx & (Lsz - 1);
        int b = bh / Hn, h = bh % Hn;
        __syncthreads();
        ((float4*)xs)[tid] = ((const float4*)(x + (size_t)(b * Lsz + l) * Dsz))[tid];
        __syncthreads();
        float ss = 0.f;
#pragma unroll
        for (int d0 = 0; d0 < 8; d0++) {
            int d = wid * 8 + d0;
            const float4* wr = (const float4*)(Wq + (size_t)(h * HDs + d) * Dsz);
            float s = 0.f;
#pragma unroll
            for (int j = 0; j < 8; j++) {
                float4 wv = wr[lane + j * 32];
                float4 xv = ((const float4*)xs)[lane + j * 32];
                s += wv.x*xv.x + wv.y*xv.y + wv.z*xv.z + wv.w*xv.w;
            }
#pragma unroll
            for (int o = 16; o; o >>= 1) s += __shfl_xor_sync(0xffffffffu, s, o);
            if (lane == 0) {
                float qi = s + bq[h * HDs + d];
                ss += qi * qi;
            }
        }
        if (lane == 0) acc[wid] = ss;
        __syncthreads();
        if (tid == 0)
            norms[idx] = ((acc[0] + acc[1]) + (acc[2] + acc[3]))
                       + ((acc[4] + acc[5]) + (acc[6] + acc[7]));
    }
}

// ---------------- exact top-k per (b,h): 512-thread bitonic --------------------
#define TOPK_T 512
__global__ __launch_bounds__(TOPK_T)
void topk_kernel(const float* __restrict__ norms, int* __restrict__ sel) {
    int bh = blockIdx.x;
    __shared__ float s[Lsz];
    __shared__ int cnt_out;
    __shared__ int cnt_gt;
    const float* nb = norms + (size_t)bh * Lsz;
    int tid = threadIdx.x;
    for (int i = tid; i < Lsz; i += TOPK_T) s[i] = nb[i];
    __syncthreads();
    for (int ksz = 2; ksz <= Lsz; ksz <<= 1) {
        for (int j = ksz >> 1; j > 0; j >>= 1) {
            for (int idx = tid; idx < Lsz; idx += TOPK_T) {
                int ixj = idx ^ j;
                if (ixj > idx) {
                    bool desc = ((idx & ksz) == 0);
                    float a = s[idx], bb = s[ixj];
                    bool sw = desc ? (a < bb) : (a > bb);
                    if (sw) { s[idx] = bb; s[ixj] = a; }
                }
            }
            __syncthreads();
        }
    }
    float t = s[KTOPn - 1];
    if (tid == 0) { cnt_out = 0; cnt_gt = 0; }
    __syncthreads();
    int lc = 0;
    for (int i = tid; i < Lsz; i += TOPK_T) lc += (nb[i] > t) ? 1 : 0;
    atomicAdd(&cnt_gt, lc);
    __syncthreads();
    int need = KTOPn - cnt_gt;
    for (int i = tid; i < Lsz; i += TOPK_T) {
        float v = nb[i];
        bool pick = false;
        if (v > t) pick = true;
        else if (v == t) {
            int eqb = 0;
            for (int jj = 0; jj < i; jj++) eqb += (nb[jj] == t) ? 1 : 0;
            pick = (eqb < need);
        }
        if (pick) {
            int p = atomicAdd(&cnt_out, 1);
            sel[(size_t)bh * KTOPn + p] = i;
        }
    }
}

// ---------------- V column means -----------------------------------------------
__global__ void vpartial_kernel(const float* __restrict__ V, float* __restrict__ part) {
    int b = blockIdx.x >> 5, c = blockIdx.x & 31;
    int d = threadIdx.x;
    float sum = 0.f;
#pragma unroll 4
    for (int r = 0; r < 64; r++)
        sum += V[(size_t)(b * Lsz + c * 64 + r) * Dsz + d];
    part[(size_t)(b * 32 + c) * Dsz + d] = sum;
}

__global__ void vmean_kernel(const float* __restrict__ part, float* __restrict__ vm) {
    int i = blockIdx.x * 256 + threadIdx.x;
    if (i >= Bsz * Dsz) return;
    int b = i / Dsz, d = i % Dsz;
    float sum = 0.f;
#pragma unroll
    for (int c = 0; c < 32; c++) sum += part[(size_t)(b * 32 + c) * Dsz + d];
    vm[i] = sum * (1.0f / Lsz);
}

__global__ void fill_kernel(const float* __restrict__ vm, float* __restrict__ attn) {
    size_t i = (size_t)blockIdx.x * 256 + threadIdx.x;
    if (i >= (size_t)Bsz * Lsz * Dsz) return;
    int d = (int)(i % Dsz);
    int b = (int)(i / ((size_t)Lsz * Dsz));
    attn[i] = vm[b * Dsz + d];
}

// ------------- tensor-core flash attention over selected queries ---------------
__global__ __launch_bounds__(128)
void attn_tc(const float* __restrict__ Q, const float* __restrict__ K,
             const float* __restrict__ V, const int* __restrict__ sel,
             float* __restrict__ out) {
    __shared__ float QP[32][68];      // Q staging, then probs
    __shared__ float Ks[64][68];
    __shared__ float Vs[64][68];
    __shared__ float pmax[4][32], psum[4][32];
    __shared__ int   sidx[32];

    int bh = blockIdx.y, b = bh / Hn, h = bh % Hn;
    int qbase = blockIdx.x * 32;
    int tid = threadIdx.x, wid = tid >> 5, lane = tid & 31;
    int group = lane >> 2, tg = lane & 3;
    int wb = wid * 16;

    if (tid < 32)
        sidx[tid] = (qbase + tid < KTOPn) ? sel[(size_t)bh * KTOPn + qbase + tid] : -1;
    __syncthreads();

    for (int i = tid; i < 32 * 16; i += 128) {
        int r = i >> 4, c4 = (i & 15) * 4;
        float4 v = make_float4(0.f, 0.f, 0.f, 0.f);
        int sl = sidx[r];
        if (sl >= 0) v = *(const float4*)&Q[(size_t)(b * Lsz + sl) * Dsz + h * HDs + c4];
        unsigned t0, t1, t2, t3;
        CVT_TF32(t0, v.x * SCALE); CVT_TF32(t1, v.y * SCALE);
        CVT_TF32(t2, v.z * SCALE); CVT_TF32(t3, v.w * SCALE);
        QP[r][c4+0] = __uint_as_float(t0); QP[r][c4+1] = __uint_as_float(t1);
        QP[r][c4+2] = __uint_as_float(t2); QP[r][c4+3] = __uint_as_float(t3);
    }
    __syncthreads();

    unsigned aQ[2][8][4];
#pragma unroll
    for (int mt = 0; mt < 2; mt++)
#pragma unroll
        for (int ks = 0; ks < 8; ks++) {
            int row = mt * 16 + group, k = ks * 8;
            aQ[mt][ks][0] = __float_as_uint(QP[row][k + tg]);
            aQ[mt][ks][1] = __float_as_uint(QP[row + 8][k + tg]);
            aQ[mt][ks][2] = __float_as_uint(QP[row][k + tg + 4]);
            aQ[mt][ks][3] = __float_as_uint(QP[row + 8][k + tg + 4]);
        }
    __syncthreads();

    float m_s[4] = { -INFINITY, -INFINITY, -INFINITY, -INFINITY };
    float l_s[4] = { 0.f, 0.f, 0.f, 0.f };
    float O[2][2][4];
#pragma unroll
    for (int mt = 0; mt < 2; mt++)
#pragma unroll
        for (int nt = 0; nt < 2; nt++)
#pragma unroll
            for (int i = 0; i < 4; i++) O[mt][nt][i] = 0.f;

    for (int kt = 0; kt < Lsz / 64; kt++) {
        __syncthreads();
        for (int i = tid; i < 64 * 16; i += 128) {
            int r = i >> 4, c4 = (i & 15) * 4;
            size_t gro = (size_t)(b * Lsz + kt * 64 + r) * Dsz + h * HDs + c4;
            float4 kv = *(const float4*)&K[gro];
            float4 vv = *(const float4*)&V[gro];
            unsigned t0, t1, t2, t3;
            CVT_TF32(t0, kv.x); CVT_TF32(t1, kv.y); CVT_TF32(t2, kv.z); CVT_TF32(t3, kv.w);
            Ks[r][c4+0] = __uint_as_float(t0); Ks[r][c4+1] = __uint_as_float(t1);
            Ks[r][c4+2] = __uint_as_float(t2); Ks[r][c4+3] = __uint_as_float(t3);
            CVT_TF32(t0, vv.x); CVT_TF32(t1, vv.y); CVT_TF32(t2, vv.z); CVT_TF32(t3, vv.w);
            Vs[r][c4+0] = __uint_as_float(t0); Vs[r][c4+1] = __uint_as_float(t1);
            Vs[r][c4+2] = __uint_as_float(t2); Vs[r][c4+3] = __uint_as_float(t3);
        }
        __syncthreads();

        float s[2][2][4];
#pragma unroll
        for (int mt = 0; mt < 2; mt++)
#pragma unroll
            for (int nt = 0; nt < 2; nt++)
#pragma unroll
                for (int i = 0; i < 4; i++) s[mt][nt][i] = 0.f;
#pragma unroll
        for (int nt = 0; nt < 2; nt++)
#pragma unroll
            for (int ks = 0; ks < 8; ks++) {
                int n = wb + nt * 8 + group, k = ks * 8;
                unsigned bb[2];
                bb[0] = __float_as_uint(Ks[n][k + tg]);
                bb[1] = __float_as_uint(Ks[n][k + tg + 4]);
                MMA_TF32(s[0][nt], aQ[0][ks], bb);
                MMA_TF32(s[1][nt], aQ[1][ks], bb);
            }

        float lm[4];
#pragma unroll
        for (int mt = 0; mt < 2; mt++)
#pragma unroll
            for (int hh = 0; hh < 2; hh++) {
                float m = fmaxf(fmaxf(s[mt][0][hh*2], s[mt][0][hh*2+1]),
                                fmaxf(s[mt][1][hh*2], s[mt][1][hh*2+1]));
                m = fmaxf(m, __shfl_xor_sync(0xffffffffu, m, 1));
                m = fmaxf(m, __shfl_xor_sync(0xffffffffu, m, 2));
                lm[mt*2+hh] = m;
            }
        if (tg == 0) {
#pragma unroll
            for (int mt = 0; mt < 2; mt++)
#pragma unroll
                for (int hh = 0; hh < 2; hh++)
                    pmax[wid][mt*16 + hh*8 + group] = lm[mt*2+hh];
        }
        __syncthreads();

        float mnew[4], corr[4];
#pragma unroll
        for (int mt = 0; mt < 2; mt++)
#pragma unroll
            for (int hh = 0; hh < 2; hh++) {
                int r = mt*16 + hh*8 + group, idx = mt*2+hh;
                float g = fmaxf(fmaxf(pmax[0][r], pmax[1][r]),
                                fmaxf(pmax[2][r], pmax[3][r]));
                mnew[idx] = fmaxf(m_s[idx], g);
                corr[idx] = __expf(m_s[idx] - mnew[idx]);
                m_s[idx] = mnew[idx];
            }

        float ls[4] = { 0.f, 0.f, 0.f, 0.f };
#pragma unroll
        for (int mt = 0; mt < 2; mt++)
#pragma unroll
            for (int hh = 0; hh < 2; hh++) {
                int r = mt*16 + hh*8 + group, idx = mt*2+hh;
#pragma unroll
                for (int nt = 0; nt < 2; nt++) {
                    float p0 = __expf(s[mt][nt][hh*2]   - mnew[idx]);
                    float p1 = __expf(s[mt][nt][hh*2+1] - mnew[idx]);
                    unsigned u0, u1;
                    CVT_TF32(u0, p0); CVT_TF32(u1, p1);
                    int col = wb + nt*8 + tg*2;
                    QP[r][col]   = __uint_as_float(u0);
                    QP[r][col+1] = __uint_as_float(u1);
                    ls[idx] += p0 + p1;
                }
            }
#pragma unroll
        for (int idx = 0; idx < 4; idx++) {
            float v = ls[idx];
            v += __shfl_xor_sync(0xffffffffu, v, 1);
            v += __shfl_xor_sync(0xffffffffu, v, 2);
            ls[idx] = v;
        }
        if (tg == 0) {
#pragma unroll
            for (int mt = 0; mt < 2; mt++)
#pragma unroll
                for (int hh = 0; hh < 2; hh++)
                    psum[wid][mt*16 + hh*8 + group] = ls[mt*2+hh];
        }
        __syncthreads();

#pragma unroll
        for (int mt = 0; mt < 2; mt++)
#pragma unroll
            for (int hh = 0; hh < 2; hh++) {
                int r = mt*16 + hh*8 + group, idx = mt*2+hh;
                float ts = psum[0][r] + psum[1][r] + psum[2][r] + psum[3][r];
                l_s[idx] = l_s[idx] * corr[idx] + ts;
            }

#pragma unroll
        for (int mt = 0; mt < 2; mt++)
#pragma unroll
            for (int nt = 0; nt < 2; nt++) {
                O[mt][nt][0] *= corr[mt*2];   O[mt][nt][1] *= corr[mt*2];
                O[mt][nt][2] *= corr[mt*2+1]; O[mt][nt][3] *= corr[mt*2+1];
            }
#pragma unroll
        for (int ks = 0; ks < 8; ks++) {
            int k = ks * 8;
            unsigned aP[2][4];
#pragma unroll
            for (int mt = 0; mt < 2; mt++) {
                int row = mt*16 + group;
                aP[mt][0] = __float_as_uint(QP[row][k + tg]);
                aP[mt][1] = __float_as_uint(QP[row + 8][k + tg]);
                aP[mt][2] = __float_as_uint(QP[row][k + tg + 4]);
                aP[mt][3] = __float_as_uint(QP[row + 8][k + tg + 4]);
            }
#pragma unroll
            for (int nt = 0; nt < 2; nt++) {
                unsigned bb[2];
                bb[0] = __float_as_uint(Vs[k + tg][wb + nt*8 + group]);
                bb[1] = __float_as_uint(Vs[k + tg + 4][wb + nt*8 + group]);
                MMA_TF32(O[0][nt], aP[0], bb);
                MMA_TF32(O[1][nt], aP[1], bb);
            }
        }
    }

#pragma unroll
    for (int mt = 0; mt < 2; mt++)
#pragma unroll
        for (int hh = 0; hh < 2; hh++) {
            int r = mt*16 + hh*8 + group, idx = mt*2+hh;
            if (qbase + r < KTOPn) {
                int sl = sidx[r];
                float inv = 1.0f / l_s[idx];
#pragma unroll
                for (int nt = 0; nt < 2; nt++) {
                    int col = h * HDs + wb + nt*8 + tg*2;
                    *(float2*)&out[(size_t)(b * Lsz + sl) * Dsz + col] =
                        make_float2(O[mt][nt][hh*2] * inv, O[mt][nt][hh*2+1] * inv);
                }
            }
        }
}

// ---------------- launch: two-sided fork-join ----------------------------------
// main:  gemmV --evV--> gemmQ --evQ--> gemmK ---(wait evFill,evSel)--> attn -> gemmO
// side1:      \-> vpartial -> vmean -> fill --evFill (hides under gemmQ+gemmK)
// side2:                  \-> qnorm..topk --evSel     (hides under gemmK)
extern "C" void kernel_launch(void* const* d_in, const int* in_sizes, int n_in,
                              void* d_out, int out_size) {
    const float* x  = (const float*)d_in[0];
    const float* Wq = (const float*)d_in[1];
    const float* bq = (const float*)d_in[2];
    const float* Wk = (const float*)d_in[3];
    const float* bk = (const float*)d_in[4];
    const float* Wv = (const float*)d_in[5];
    const float* bv = (const float*)d_in[6];
    const float* Wo = (const float*)d_in[7];
    const float* bo = (const float*)d_in[8];
    float* out = (float*)d_out;

    float *pQ, *pK, *pV, *pA, *pN, *pPart, *pM, *pT;
    int *pS, *pL, *pC;
    cudaGetSymbolAddress((void**)&pQ, g_Q);
    cudaGetSymbolAddress((void**)&pK, g_K);
    cudaGetSymbolAddress((void**)&pV, g_V);
    cudaGetSymbolAddress((void**)&pA, g_A);
    cudaGetSymbolAddress((void**)&pN, g_norm);
    cudaGetSymbolAddress((void**)&pS, g_sel);
    cudaGetSymbolAddress((void**)&pPart, g_part);
    cudaGetSymbolAddress((void**)&pM, g_vmean);
    cudaGetSymbolAddress((void**)&pT, g_thr);
    cudaGetSymbolAddress((void**)&pL, g_list);
    cudaGetSymbolAddress((void**)&pC, g_count);

    const int M = Bsz * Lsz;   // 4096
    dim3 gemm_grid(Dsz / 128, M / 128);
    cudaStream_t s1 = g_ov.side1, s2 = g_ov.side2;

    // V first so its consumers fork earliest
    gemm_1xtf32<<<gemm_grid, 256>>>(x, Wv, bv, pV, M, Dsz, Dsz);
    cudaEventRecord(g_ov.evV, 0);

    // side1: vmean chain (depends only on V); fill writes all of pA
    cudaStreamWaitEvent(s1, g_ov.evV, 0);
    vpartial_kernel<<<Bsz * 32, 1024, 0, s1>>>(pV, pPart);
    vmean_kernel<<<(Bsz * Dsz + 255) / 256, 256, 0, s1>>>(pPart, pM);
    fill_kernel<<<(Bsz * Lsz * Dsz) / 256, 256, 0, s1>>>(pM, pA);
    cudaEventRecord(g_ov.evFill, s1);

    gemm_1xtf32<<<gemm_grid, 256>>>(x, Wq, bq, pQ, M, Dsz, Dsz);
    cudaEventRecord(g_ov.evQ, 0);

    // side2: exact-boundary top-k chain (depends only on Q)
    cudaStreamWaitEvent(s2, g_ov.evQ, 0);
    qnorm_kernel<<<(BHn * Lsz) / 8, 256, 0, s2>>>(pQ, pN, pC);
    hist_thresh_kernel<<<BHn, 256, 0, s2>>>(pN, pT);
    flag_kernel<<<(BHn * Lsz) / 256, 256, 0, s2>>>(pN, pT, pL, pC);
    refine_kernel<<<512, 256, 0, s2>>>(x, Wq, bq, pL, pC, pN);
    topk_kernel<<<BHn, TOPK_T, 0, s2>>>(pN, pS);
    cudaEventRecord(g_ov.evSel, s2);

    gemm_1xtf32<<<gemm_grid, 256>>>(x, Wk, bk, pK, M, Dsz, Dsz);

    // join: attn needs fill-complete pA and sel
    cudaStreamWaitEvent(0, g_ov.evFill, 0);
    cudaStreamWaitEvent(0, g_ov.evSel, 0);
    attn_tc<<<dim3((KTOPn + 31) / 32, BHn), 128>>>(pQ, pK, pV, pS, pA);

    gemm_1xtf32<<<gemm_grid, 256>>>(pA, Wo, bo, out, M, Dsz, Dsz);
}

// round 17
// speedup vs baseline: 1.1202x; 1.1202x over previous
#include <cuda_runtime.h>
#include <math.h>

#define Bsz 2
#define Lsz 2048
#define Dsz 1024
#define Hn  16
#define HDs 64
#define KTOPn 409
#define BHn (Bsz*Hn)
#define SCALE 0.125f
#define HBINS 2048
#define HBINW 0.08f
#define RMARGIN 0.2f

// ---------------- scratch (device globals: allocation-free rule) ----------------
__device__ float g_Q[Bsz*Lsz*Dsz];
__device__ float g_K[Bsz*Lsz*Dsz];
__device__ float g_V[Bsz*Lsz*Dsz];
__device__ float g_A[Bsz*Lsz*Dsz];       // attention output, [B,L,H*HD]
__device__ float g_norm[BHn*Lsz];
__device__ int   g_sel[BHn*KTOPn];
__device__ float g_part[Bsz*32*Dsz];
__device__ float g_vmean[Bsz*Dsz];
__device__ float g_thr[BHn];
__device__ int   g_list[BHn*Lsz];
__device__ int   g_count[1];

// Side stream + events for fork-join overlap (R15-proven). Static init: no
// device memory, identical launched work every call -> deterministic & capturable.
// R16 lesson: do NOT overlap the vmean/fill chain with GEMMs (16MB streaming
// writes thrash L2 and displace GEMM CTAs; cost ~70us vs 25us serial).
struct OverlapRes {
    cudaStream_t side;
    cudaEvent_t evQ, evSel;
    OverlapRes() {
        cudaStreamCreateWithFlags(&side, cudaStreamNonBlocking);
        cudaEventCreateWithFlags(&evQ, cudaEventDisableTiming);
        cudaEventCreateWithFlags(&evSel, cudaEventDisableTiming);
    }
};
static OverlapRes g_ov;

#define CVT_TF32(dst, src) asm("cvt.rna.tf32.f32 %0, %1;" : "=r"(dst) : "f"(src))

#define MMA_TF32(cc, aa, bb)                                                  \
    asm volatile(                                                             \
        "mma.sync.aligned.m16n8k8.row.col.f32.tf32.tf32.f32 "                 \
        "{%0,%1,%2,%3}, {%4,%5,%6,%7}, {%8,%9}, {%0,%1,%2,%3};"               \
        : "+f"(cc[0]), "+f"(cc[1]), "+f"(cc[2]), "+f"(cc[3])                  \
        : "r"(aa[0]), "r"(aa[1]), "r"(aa[2]), "r"(aa[3]),                     \
          "r"(bb[0]), "r"(bb[1]))

// ------------- 1xTF32 tensor-core GEMM (R12-proven, frozen) --------------------
__global__ __launch_bounds__(256)
void gemm_1xtf32(const float* __restrict__ A, const float* __restrict__ W,
                 const float* __restrict__ bias, float* __restrict__ C,
                 int M, int N, int K) {
    __shared__ float As[128][36];
    __shared__ float Bs[128][36];
    int tid = threadIdx.x;
    int bm = blockIdx.y * 128, bn = blockIdx.x * 128;
    int wid = tid >> 5, lane = tid & 31;
    int wm = (wid & 3) * 32, wn = (wid >> 2) * 64;
    int group = lane >> 2, tg = lane & 3;

    float c[2][8][4];
#pragma unroll
    for (int mt = 0; mt < 2; mt++)
#pragma unroll
        for (int nt = 0; nt < 8; nt++)
#pragma unroll
            for (int i = 0; i < 4; i++) c[mt][nt][i] = 0.f;

    for (int kk = 0; kk < K; kk += 32) {
#pragma unroll
        for (int i = 0; i < 4; i++) {
            int lin = tid + i * 256;
            int r = lin >> 3, c4 = (lin & 7) * 4;
            float4 av = *(const float4*)&A[(size_t)(bm + r) * K + kk + c4];
            float4 wv = *(const float4*)&W[(size_t)(bn + r) * K + kk + c4];
            uint4 at, bt;
            CVT_TF32(at.x, av.x); CVT_TF32(at.y, av.y);
            CVT_TF32(at.z, av.z); CVT_TF32(at.w, av.w);
            CVT_TF32(bt.x, wv.x); CVT_TF32(bt.y, wv.y);
            CVT_TF32(bt.z, wv.z); CVT_TF32(bt.w, wv.w);
            *(uint4*)&As[r][c4] = at;
            *(uint4*)&Bs[r][c4] = bt;
        }
        __syncthreads();

#pragma unroll
        for (int ks = 0; ks < 4; ks++) {
            int k = ks * 8;
            unsigned a[2][4], b[8][2];
#pragma unroll
            for (int mt = 0; mt < 2; mt++) {
                int row = wm + mt * 16 + group;
                a[mt][0] = __float_as_uint(As[row][k + tg]);
                a[mt][1] = __float_as_uint(As[row + 8][k + tg]);
                a[mt][2] = __float_as_uint(As[row][k + tg + 4]);
                a[mt][3] = __float_as_uint(As[row + 8][k + tg + 4]);
            }
#pragma unroll
            for (int nt = 0; nt < 8; nt++) {
                int col = wn + nt * 8 + group;
                b[nt][0] = __float_as_uint(Bs[col][k + tg]);
                b[nt][1] = __float_as_uint(Bs[col][k + tg + 4]);
            }
#pragma unroll
            for (int mt = 0; mt < 2; mt++)
#pragma unroll
                for (int nt = 0; nt < 8; nt++)
                    MMA_TF32(c[mt][nt], a[mt], b[nt]);
        }
        __syncthreads();
    }

#pragma unroll
    for (int mt = 0; mt < 2; mt++) {
        int row0 = bm + wm + mt * 16 + group;
#pragma unroll
        for (int nt = 0; nt < 8; nt++) {
            int col = bn + wn + nt * 8 + tg * 2;
            float b0 = bias[col], b1 = bias[col + 1];
            *(float2*)&C[(size_t)row0 * N + col] =
                make_float2(c[mt][nt][0] + b0, c[mt][nt][1] + b1);
            *(float2*)&C[(size_t)(row0 + 8) * N + col] =
                make_float2(c[mt][nt][2] + b0, c[mt][nt][3] + b1);
        }
    }
}

// ---------------- per-(b,h,l) squared L2 norm of q; also zeroes refine counter -
__global__ void qnorm_kernel(const float* __restrict__ Q, float* __restrict__ norms,
                             int* __restrict__ cnt) {
    if (blockIdx.x == 0 && threadIdx.x == 0) cnt[0] = 0;
    int gw = blockIdx.x * 8 + (threadIdx.x >> 5);
    int lane = threadIdx.x & 31;
    if (gw >= BHn * Lsz) return;
    int l = gw % Lsz;
    int h = (gw / Lsz) % Hn;
    int b = gw / (Lsz * Hn);
    const float* row = Q + (size_t)(b * Lsz + l) * Dsz + h * HDs;
    float v0 = row[lane], v1 = row[lane + 32];
    float ss = v0*v0 + v1*v1;
#pragma unroll
    for (int o = 16; o; o >>= 1) ss += __shfl_xor_sync(0xffffffffu, ss, o);
    if (lane == 0) norms[(b * Hn + h) * Lsz + l] = ss;
}

// ---------------- histogram threshold per (b,h): t within 0.04 of 409th -------
__global__ void hist_thresh_kernel(const float* __restrict__ norms,
                                   float* __restrict__ thr) {
    __shared__ int hist[HBINS];
    __shared__ int chunk[256];
    int bh = blockIdx.x, tid = threadIdx.x;
    const float* nb = norms + (size_t)bh * Lsz;
#pragma unroll
    for (int i = 0; i < HBINS / 256; i++) hist[tid + i * 256] = 0;
    __syncthreads();
    for (int i = tid; i < Lsz; i += 256) {
        int bin = (int)(nb[i] * (1.0f / HBINW));
        bin = min(HBINS - 1, max(0, bin));
        atomicAdd(&hist[bin], 1);
    }
    __syncthreads();
    int cs = 0;
#pragma unroll
    for (int j = 0; j < 8; j++) cs += hist[tid * 8 + j];
    chunk[tid] = cs;
    __syncthreads();
    if (tid == 0) {
        int cum = 0, binfound = 0;
        for (int cidx = 255; cidx >= 0; cidx--) {
            if (cum + chunk[cidx] >= KTOPn) {
                for (int bin = cidx * 8 + 7; bin >= cidx * 8; bin--) {
                    cum += hist[bin];
                    if (cum >= KTOPn) { binfound = bin; break; }
                }
                break;
            }
            cum += chunk[cidx];
        }
        thr[bh] = (binfound + 0.5f) * HBINW;
    }
}

// ---------------- flag boundary-uncertain rows into compact worklist -----------
__global__ void flag_kernel(const float* __restrict__ norms, const float* __restrict__ thr,
                            int* __restrict__ list, int* __restrict__ cnt) {
    int idx = blockIdx.x * 256 + threadIdx.x;
    if (idx >= BHn * Lsz) return;
    float n = norms[idx];
    float t = thr[idx >> 11];
    if (fabsf(n - t) < RMARGIN) {
        int p = atomicAdd(cnt, 1);
        list[p] = idx;
    }
}

// ---------------- exact fp32 norm recompute for flagged rows (coalesced) -------
__global__ __launch_bounds__(256)
void refine_kernel(const float* __restrict__ x, const float* __restrict__ Wq,
                   const float* __restrict__ bq, const int* __restrict__ list,
                   const int* __restrict__ cnt, float* __restrict__ norms) {
    __shared__ float xs[Dsz];
    __shared__ float acc[8];
    int tid = threadIdx.x, wid = tid >> 5, lane = tid & 31;
    int n_items = cnt[0];
    for (int ii = blockIdx.x; ii < n_items; ii += gridDim.x) {
        int idx = list[ii];
        int bh = idx >> 11, l = idx & (Lsz - 1);
        int b = bh / Hn, h = bh % Hn;
        __syncthreads();
        ((float4*)xs)[tid] = ((const float4*)(x + (size_t)(b * Lsz + l) * Dsz))[tid];
        __syncthreads();
        float ss = 0.f;
#pragma unroll
        for (int d0 = 0; d0 < 8; d0++) {
            int d = wid * 8 + d0;
            const float4* wr = (const float4*)(Wq + (size_t)(h * HDs + d) * Dsz);
            float s = 0.f;
#pragma unroll
            for (int j = 0; j < 8; j++) {
                float4 wv = wr[lane + j * 32];
                float4 xv = ((const float4*)xs)[lane + j * 32];
                s += wv.x*xv.x + wv.y*xv.y + wv.z*xv.z + wv.w*xv.w;
            }
#pragma unroll
            for (int o = 16; o; o >>= 1) s += __shfl_xor_sync(0xffffffffu, s, o);
            if (lane == 0) {
                float qi = s + bq[h * HDs + d];
                ss += qi * qi;
            }
        }
        if (lane == 0) acc[wid] = ss;
        __syncthreads();
        if (tid == 0)
            norms[idx] = ((acc[0] + acc[1]) + (acc[2] + acc[3]))
                       + ((acc[4] + acc[5]) + (acc[6] + acc[7]));
    }
}

// ---------------- exact top-k per (b,h): 512-thread bitonic --------------------
#define TOPK_T 512
__global__ __launch_bounds__(TOPK_T)
void topk_kernel(const float* __restrict__ norms, int* __restrict__ sel) {
    int bh = blockIdx.x;
    __shared__ float s[Lsz];
    __shared__ int cnt_out;
    __shared__ int cnt_gt;
    const float* nb = norms + (size_t)bh * Lsz;
    int tid = threadIdx.x;
    for (int i = tid; i < Lsz; i += TOPK_T) s[i] = nb[i];
    __syncthreads();
    for (int ksz = 2; ksz <= Lsz; ksz <<= 1) {
        for (int j = ksz >> 1; j > 0; j >>= 1) {
            for (int idx = tid; idx < Lsz; idx += TOPK_T) {
                int ixj = idx ^ j;
                if (ixj > idx) {
                    bool desc = ((idx & ksz) == 0);
                    float a = s[idx], bb = s[ixj];
                    bool sw = desc ? (a < bb) : (a > bb);
                    if (sw) { s[idx] = bb; s[ixj] = a; }
                }
            }
            __syncthreads();
        }
    }
    float t = s[KTOPn - 1];
    if (tid == 0) { cnt_out = 0; cnt_gt = 0; }
    __syncthreads();
    int lc = 0;
    for (int i = tid; i < Lsz; i += TOPK_T) lc += (nb[i] > t) ? 1 : 0;
    atomicAdd(&cnt_gt, lc);
    __syncthreads();
    int need = KTOPn - cnt_gt;
    for (int i = tid; i < Lsz; i += TOPK_T) {
        float v = nb[i];
        bool pick = false;
        if (v > t) pick = true;
        else if (v == t) {
            int eqb = 0;
            for (int jj = 0; jj < i; jj++) eqb += (nb[jj] == t) ? 1 : 0;
            pick = (eqb < need);
        }
        if (pick) {
            int p = atomicAdd(&cnt_out, 1);
            sel[(size_t)bh * KTOPn + p] = i;
        }
    }
}

// ---------------- V column means -----------------------------------------------
__global__ void vpartial_kernel(const float* __restrict__ V, float* __restrict__ part) {
    int b = blockIdx.x >> 5, c = blockIdx.x & 31;
    int d = threadIdx.x;
    float sum = 0.f;
#pragma unroll 4
    for (int r = 0; r < 64; r++)
        sum += V[(size_t)(b * Lsz + c * 64 + r) * Dsz + d];
    part[(size_t)(b * 32 + c) * Dsz + d] = sum;
}

__global__ void vmean_kernel(const float* __restrict__ part, float* __restrict__ vm) {
    int i = blockIdx.x * 256 + threadIdx.x;
    if (i >= Bsz * Dsz) return;
    int b = i / Dsz, d = i % Dsz;
    float sum = 0.f;
#pragma unroll
    for (int c = 0; c < 32; c++) sum += part[(size_t)(b * 32 + c) * Dsz + d];
    vm[i] = sum * (1.0f / Lsz);
}

// Fill every row with vmean — float4 stores (4x fewer instructions than scalar;
// the scalar version measured 11.7us at 31% issue, instruction-bound).
__global__ void fill_kernel(const float* __restrict__ vm, float* __restrict__ attn) {
    size_t i = (size_t)blockIdx.x * 256 + threadIdx.x;   // float4 index
    if (i >= (size_t)(Bsz * Lsz * Dsz / 4)) return;
    int d4 = (int)(i % (Dsz / 4));
    int b = (int)(i / ((size_t)Lsz * (Dsz / 4)));
    ((float4*)attn)[i] = ((const float4*)vm)[b * (Dsz / 4) + d4];
}

// ------------- tensor-core flash attention over selected queries ---------------
__global__ __launch_bounds__(128)
void attn_tc(const float* __restrict__ Q, const float* __restrict__ K,
             const float* __restrict__ V, const int* __restrict__ sel,
             float* __restrict__ out) {
    __shared__ float QP[32][68];      // Q staging, then probs
    __shared__ float Ks[64][68];
    __shared__ float Vs[64][68];
    __shared__ float pmax[4][32], psum[4][32];
    __shared__ int   sidx[32];

    int bh = blockIdx.y, b = bh / Hn, h = bh % Hn;
    int qbase = blockIdx.x * 32;
    int tid = threadIdx.x, wid = tid >> 5, lane = tid & 31;
    int group = lane >> 2, tg = lane & 3;
    int wb = wid * 16;

    if (tid < 32)
        sidx[tid] = (qbase + tid < KTOPn) ? sel[(size_t)bh * KTOPn + qbase + tid] : -1;
    __syncthreads();

    for (int i = tid; i < 32 * 16; i += 128) {
        int r = i >> 4, c4 = (i & 15) * 4;
        float4 v = make_float4(0.f, 0.f, 0.f, 0.f);
        int sl = sidx[r];
        if (sl >= 0) v = *(const float4*)&Q[(size_t)(b * Lsz + sl) * Dsz + h * HDs + c4];
        unsigned t0, t1, t2, t3;
        CVT_TF32(t0, v.x * SCALE); CVT_TF32(t1, v.y * SCALE);
        CVT_TF32(t2, v.z * SCALE); CVT_TF32(t3, v.w * SCALE);
        QP[r][c4+0] = __uint_as_float(t0); QP[r][c4+1] = __uint_as_float(t1);
        QP[r][c4+2] = __uint_as_float(t2); QP[r][c4+3] = __uint_as_float(t3);
    }
    __syncthreads();

    unsigned aQ[2][8][4];
#pragma unroll
    for (int mt = 0; mt < 2; mt++)
#pragma unroll
        for (int ks = 0; ks < 8; ks++) {
            int row = mt * 16 + group, k = ks * 8;
            aQ[mt][ks][0] = __float_as_uint(QP[row][k + tg]);
            aQ[mt][ks][1] = __float_as_uint(QP[row + 8][k + tg]);
            aQ[mt][ks][2] = __float_as_uint(QP[row][k + tg + 4]);
            aQ[mt][ks][3] = __float_as_uint(QP[row + 8][k + tg + 4]);
        }
    __syncthreads();

    float m_s[4] = { -INFINITY, -INFINITY, -INFINITY, -INFINITY };
    float l_s[4] = { 0.f, 0.f, 0.f, 0.f };
    float O[2][2][4];
#pragma unroll
    for (int mt = 0; mt < 2; mt++)
#pragma unroll
        for (int nt = 0; nt < 2; nt++)
#pragma unroll
            for (int i = 0; i < 4; i++) O[mt][nt][i] = 0.f;

    for (int kt = 0; kt < Lsz / 64; kt++) {
        __syncthreads();
        for (int i = tid; i < 64 * 16; i += 128) {
            int r = i >> 4, c4 = (i & 15) * 4;
            size_t gro = (size_t)(b * Lsz + kt * 64 + r) * Dsz + h * HDs + c4;
            float4 kv = *(const float4*)&K[gro];
            float4 vv = *(const float4*)&V[gro];
            unsigned t0, t1, t2, t3;
            CVT_TF32(t0, kv.x); CVT_TF32(t1, kv.y); CVT_TF32(t2, kv.z); CVT_TF32(t3, kv.w);
            Ks[r][c4+0] = __uint_as_float(t0); Ks[r][c4+1] = __uint_as_float(t1);
            Ks[r][c4+2] = __uint_as_float(t2); Ks[r][c4+3] = __uint_as_float(t3);
            CVT_TF32(t0, vv.x); CVT_TF32(t1, vv.y); CVT_TF32(t2, vv.z); CVT_TF32(t3, vv.w);
            Vs[r][c4+0] = __uint_as_float(t0); Vs[r][c4+1] = __uint_as_float(t1);
            Vs[r][c4+2] = __uint_as_float(t2); Vs[r][c4+3] = __uint_as_float(t3);
        }
        __syncthreads();

        float s[2][2][4];
#pragma unroll
        for (int mt = 0; mt < 2; mt++)
#pragma unroll
            for (int nt = 0; nt < 2; nt++)
#pragma unroll
                for (int i = 0; i < 4; i++) s[mt][nt][i] = 0.f;
#pragma unroll
        for (int nt = 0; nt < 2; nt++)
#pragma unroll
            for (int ks = 0; ks < 8; ks++) {
                int n = wb + nt * 8 + group, k = ks * 8;
                unsigned bb[2];
                bb[0] = __float_as_uint(Ks[n][k + tg]);
                bb[1] = __float_as_uint(Ks[n][k + tg + 4]);
                MMA_TF32(s[0][nt], aQ[0][ks], bb);
                MMA_TF32(s[1][nt], aQ[1][ks], bb);
            }

        float lm[4];
#pragma unroll
        for (int mt = 0; mt < 2; mt++)
#pragma unroll
            for (int hh = 0; hh < 2; hh++) {
                float m = fmaxf(fmaxf(s[mt][0][hh*2], s[mt][0][hh*2+1]),
                                fmaxf(s[mt][1][hh*2], s[mt][1][hh*2+1]));
                m = fmaxf(m, __shfl_xor_sync(0xffffffffu, m, 1));
                m = fmaxf(m, __shfl_xor_sync(0xffffffffu, m, 2));
                lm[mt*2+hh] = m;
            }
        if (tg == 0) {
#pragma unroll
            for (int mt = 0; mt < 2; mt++)
#pragma unroll
                for (int hh = 0; hh < 2; hh++)
                    pmax[wid][mt*16 + hh*8 + group] = lm[mt*2+hh];
        }
        __syncthreads();

        float mnew[4], corr[4];
#pragma unroll
        for (int mt = 0; mt < 2; mt++)
#pragma unroll
            for (int hh = 0; hh < 2; hh++) {
                int r = mt*16 + hh*8 + group, idx = mt*2+hh;
                float g = fmaxf(fmaxf(pmax[0][r], pmax[1][r]),
                                fmaxf(pmax[2][r], pmax[3][r]));
                mnew[idx] = fmaxf(m_s[idx], g);
                corr[idx] = __expf(m_s[idx] - mnew[idx]);
                m_s[idx] = mnew[idx];
            }

        float ls[4] = { 0.f, 0.f, 0.f, 0.f };
#pragma unroll
        for (int mt = 0; mt < 2; mt++)
#pragma unroll
            for (int hh = 0; hh < 2; hh++) {
                int r = mt*16 + hh*8 + group, idx = mt*2+hh;
#pragma unroll
                for (int nt = 0; nt < 2; nt++) {
                    float p0 = __expf(s[mt][nt][hh*2]   - mnew[idx]);
                    float p1 = __expf(s[mt][nt][hh*2+1] - mnew[idx]);
                    unsigned u0, u1;
                    CVT_TF32(u0, p0); CVT_TF32(u1, p1);
                    int col = wb + nt*8 + tg*2;
                    QP[r][col]   = __uint_as_float(u0);
                    QP[r][col+1] = __uint_as_float(u1);
                    ls[idx] += p0 + p1;
                }
            }
#pragma unroll
        for (int idx = 0; idx < 4; idx++) {
            float v = ls[idx];
            v += __shfl_xor_sync(0xffffffffu, v, 1);
            v += __shfl_xor_sync(0xffffffffu, v, 2);
            ls[idx] = v;
        }
        if (tg == 0) {
#pragma unroll
            for (int mt = 0; mt < 2; mt++)
#pragma unroll
                for (int hh = 0; hh < 2; hh++)
                    psum[wid][mt*16 + hh*8 + group] = ls[mt*2+hh];
        }
        __syncthreads();

#pragma unroll
        for (int mt = 0; mt < 2; mt++)
#pragma unroll
            for (int hh = 0; hh < 2; hh++) {
                int r = mt*16 + hh*8 + group, idx = mt*2+hh;
                float ts = psum[0][r] + psum[1][r] + psum[2][r] + psum[3][r];
                l_s[idx] = l_s[idx] * corr[idx] + ts;
            }

#pragma unroll
        for (int mt = 0; mt < 2; mt++)
#pragma unroll
            for (int nt = 0; nt < 2; nt++) {
                O[mt][nt][0] *= corr[mt*2];   O[mt][nt][1] *= corr[mt*2];
                O[mt][nt][2] *= corr[mt*2+1]; O[mt][nt][3] *= corr[mt*2+1];
            }
#pragma unroll
        for (int ks = 0; ks < 8; ks++) {
            int k = ks * 8;
            unsigned aP[2][4];
#pragma unroll
            for (int mt = 0; mt < 2; mt++) {
                int row = mt*16 + group;
                aP[mt][0] = __float_as_uint(QP[row][k + tg]);
                aP[mt][1] = __float_as_uint(QP[row + 8][k + tg]);
                aP[mt][2] = __float_as_uint(QP[row][k + tg + 4]);
                aP[mt][3] = __float_as_uint(QP[row + 8][k + tg + 4]);
            }
#pragma unroll
            for (int nt = 0; nt < 2; nt++) {
                unsigned bb[2];
                bb[0] = __float_as_uint(Vs[k + tg][wb + nt*8 + group]);
                bb[1] = __float_as_uint(Vs[k + tg + 4][wb + nt*8 + group]);
                MMA_TF32(O[0][nt], aP[0], bb);
                MMA_TF32(O[1][nt], aP[1], bb);
            }
        }
    }

#pragma unroll
    for (int mt = 0; mt < 2; mt++)
#pragma unroll
        for (int hh = 0; hh < 2; hh++) {
            int r = mt*16 + hh*8 + group, idx = mt*2+hh;
            if (qbase + r < KTOPn) {
                int sl = sidx[r];
                float inv = 1.0f / l_s[idx];
#pragma unroll
                for (int nt = 0; nt < 2; nt++) {
                    int col = h * HDs + wb + nt*8 + tg*2;
                    *(float2*)&out[(size_t)(b * Lsz + sl) * Dsz + col] =
                        make_float2(O[mt][nt][hh*2] * inv, O[mt][nt][hh*2+1] * inv);
                }
            }
        }
}

// ---------------- launch: R15-proven fork-join ---------------------------------
// Main stream:  gemmQ --ev--> gemmK -> gemmV -> vpartial -> vmean -> fill
// Side stream:        \--> qnorm -> hist -> flag -> refine -> topk --ev--\
// Main stream:                                              (join) -> attn -> gemmO
extern "C" void kernel_launch(void* const* d_in, const int* in_sizes, int n_in,
                              void* d_out, int out_size) {
    const float* x  = (const float*)d_in[0];
    const float* Wq = (const float*)d_in[1];
    const float* bq = (const float*)d_in[2];
    const float* Wk = (const float*)d_in[3];
    const float* bk = (const float*)d_in[4];
    const float* Wv = (const float*)d_in[5];
    const float* bv = (const float*)d_in[6];
    const float* Wo = (const float*)d_in[7];
    const float* bo = (const float*)d_in[8];
    float* out = (float*)d_out;

    float *pQ, *pK, *pV, *pA, *pN, *pPart, *pM, *pT;
    int *pS, *pL, *pC;
    cudaGetSymbolAddress((void**)&pQ, g_Q);
    cudaGetSymbolAddress((void**)&pK, g_K);
    cudaGetSymbolAddress((void**)&pV, g_V);
    cudaGetSymbolAddress((void**)&pA, g_A);
    cudaGetSymbolAddress((void**)&pN, g_norm);
    cudaGetSymbolAddress((void**)&pS, g_sel);
    cudaGetSymbolAddress((void**)&pPart, g_part);
    cudaGetSymbolAddress((void**)&pM, g_vmean);
    cudaGetSymbolAddress((void**)&pT, g_thr);
    cudaGetSymbolAddress((void**)&pL, g_list);
    cudaGetSymbolAddress((void**)&pC, g_count);

    const int M = Bsz * Lsz;   // 4096
    dim3 gemm_grid(Dsz / 128, M / 128);
    cudaStream_t sd = g_ov.side;

    gemm_1xtf32<<<gemm_grid, 256>>>(x, Wq, bq, pQ, M, Dsz, Dsz);
    cudaEventRecord(g_ov.evQ, 0);

    // side stream: exact-boundary top-k chain (depends only on Q)
    cudaStreamWaitEvent(sd, g_ov.evQ, 0);
    qnorm_kernel<<<(BHn * Lsz) / 8, 256, 0, sd>>>(pQ, pN, pC);
    hist_thresh_kernel<<<BHn, 256, 0, sd>>>(pN, pT);
    flag_kernel<<<(BHn * Lsz) / 256, 256, 0, sd>>>(pN, pT, pL, pC);
    refine_kernel<<<512, 256, 0, sd>>>(x, Wq, bq, pL, pC, pN);
    topk_kernel<<<BHn, TOPK_T, 0, sd>>>(pN, pS);
    cudaEventRecord(g_ov.evSel, sd);

    // main stream: K/V projections + vmean/fill (fill stays serial: R16 showed
    // overlapping its 16MB streaming writes with GEMMs costs more than it saves)
    gemm_1xtf32<<<gemm_grid, 256>>>(x, Wk, bk, pK, M, Dsz, Dsz);
    gemm_1xtf32<<<gemm_grid, 256>>>(x, Wv, bv, pV, M, Dsz, Dsz);
    vpartial_kernel<<<Bsz * 32, 1024>>>(pV, pPart);
    vmean_kernel<<<(Bsz * Dsz + 255) / 256, 256>>>(pPart, pM);
    fill_kernel<<<(Bsz * Lsz * Dsz / 4 + 255) / 256, 256>>>(pM, pA);

    // join: attention needs sel from the side stream
    cudaStreamWaitEvent(0, g_ov.evSel, 0);
    attn_tc<<<dim3((KTOPn + 31) / 32, BHn), 128>>>(pQ, pK, pV, pS, pA);

    gemm_1xtf32<<<gemm_grid, 256>>>(pA, Wo, bo, out, M, Dsz, Dsz);
}